// round 5
// baseline (speedup 1.0000x reference)
#include <cuda_runtime.h>
#include <cstdint>

// VectorQuantize: H=1, N=32768, D=256, K=4096.
// Round 5: int8 IMMA screen, BM=256 (single wave of 128 CTAs),
//          B staged via cp.async 3-deep smem ring, A resident in smem.
//          Exact-int32 quantized argmin -> 64 candidates -> exact fp32 top-16 rescore.

#define N_TOK 32768
#define DIM   256
#define KCODE 4096
#define BM    256
#define NKT   (KCODE / 128)     // 32 k-tiles of 128 codes

#define A_WORDS  16384          // 64 KB: [mt(16)][c(8)][lane(32)][r(4)]
#define B_WORDS  8192           // 32 KB per stage: [nt(16)][c(8)][lane(32)][hk(2)]
#define NSTG     3
#define SMEM_TOTAL ((A_WORDS + NSTG * B_WORDS) * 4)

__device__ float    g_e2[KCODE];             // exact fp32 ||e||^2 (rescore)
__device__ int      g_e2s[KCODE];            // int ||q_e||^2 (screen)
__device__ uint32_t g_e8[KCODE / 8 * 8 * 32 * 2];  // B frags, 32KB-contig per k-tile
__device__ int2     g_cand[N_TOK][64];

// ---------------------------------------------------------------------------
__device__ __forceinline__ void imma16832(int c[4], uint32_t a0, uint32_t a1,
                                          uint32_t a2, uint32_t a3,
                                          uint32_t b0, uint32_t b1) {
    asm volatile(
        "mma.sync.aligned.m16n8k32.row.col.s32.s8.s8.s32 "
        "{%0,%1,%2,%3}, {%4,%5,%6,%7}, {%8,%9}, {%0,%1,%2,%3};"
        : "+r"(c[0]), "+r"(c[1]), "+r"(c[2]), "+r"(c[3])
        : "r"(a0), "r"(a1), "r"(a2), "r"(a3), "r"(b0), "r"(b1));
}
__device__ __forceinline__ int q8(float v) {
    int q = __float2int_rn(v * 32.0f);
    return max(-127, min(127, q));
}
__device__ __forceinline__ uint32_t pack4(int q0, int q1, int q2, int q3) {
    return (uint32_t)(q0 & 0xFF) | ((uint32_t)(q1 & 0xFF) << 8) |
           ((uint32_t)(q2 & 0xFF) << 16) | ((uint32_t)(q3 & 0xFF) << 24);
}
__device__ __forceinline__ uint32_t smem_u32(const void* p) {
    uint32_t a;
    asm("{ .reg .u64 t; cvta.to.shared.u64 t, %1; cvt.u32.u64 %0, t; }" : "=r"(a) : "l"(p));
    return a;
}
__device__ __forceinline__ void cp16(uint32_t sdst, const void* gsrc) {
    asm volatile("cp.async.cg.shared.global [%0], [%1], 16;"
                 :: "r"(sdst), "l"(gsrc) : "memory");
}
#define CP_COMMIT() asm volatile("cp.async.commit_group;" ::: "memory")
#define CP_WAIT2()  asm volatile("cp.async.wait_group 2;" ::: "memory")

// ---------------------------------------------------------------------------
// equant: embed -> int8 B-fragment layout (+ e2s / e2). Warp per code row.
// ---------------------------------------------------------------------------
__global__ void equant_kernel(const float* __restrict__ embed) {
    const int n    = (blockIdx.x * blockDim.x + threadIdx.x) >> 5;
    const int lane = threadIdx.x & 31;
    if (n >= KCODE) return;
    const float* row = embed + (size_t)n * DIM;

    float4 va = *(const float4*)(row + lane * 8);
    float4 vb = *(const float4*)(row + lane * 8 + 4);
    int   qa[8] = {q8(va.x), q8(va.y), q8(va.z), q8(va.w),
                   q8(vb.x), q8(vb.y), q8(vb.z), q8(vb.w)};
    float fv[8] = {va.x, va.y, va.z, va.w, vb.x, vb.y, vb.z, vb.w};

    int s2i = 0; float s2f = 0.f;
#pragma unroll
    for (int i = 0; i < 8; i++) { s2i += qa[i] * qa[i]; s2f = fmaf(fv[i], fv[i], s2f); }
#pragma unroll
    for (int o = 16; o > 0; o >>= 1) {
        s2i += __shfl_xor_sync(0xffffffffu, s2i, o);
        s2f += __shfl_xor_sync(0xffffffffu, s2f, o);
    }
    if (lane == 0) { g_e2s[n] = s2i; g_e2[n] = s2f; }

    const int nt = n >> 3, gidn = n & 7;
#pragma unroll
    for (int u = 0; u < 2; u++) {
        int k0 = lane * 8 + 4 * u;
        int c = k0 >> 5, hk = (k0 >> 4) & 1, tg = (k0 >> 2) & 3;
        uint32_t w = pack4(qa[4 * u], qa[4 * u + 1], qa[4 * u + 2], qa[4 * u + 3]);
        g_e8[(((nt * 8 + c) * 32 + gidn * 4 + tg) << 1) + hk] = w;
    }
}

// ---------------------------------------------------------------------------
// Screen: 512 threads = 16 warps = 4 wm (64 rows each) x 4 wn (4 ntiles each).
// A resident in smem; B cp.async ring (3 stages x 32KB). Two top-2 streams per
// row-slot (split by j) -> 128-code streams, identical margin to round 4.
// ---------------------------------------------------------------------------
__global__ __launch_bounds__(512, 1)
void screen_kernel(const float* __restrict__ x) {
    extern __shared__ uint32_t sm[];
    uint32_t* sA = sm;                 // A_WORDS
    uint32_t* sB = sm + A_WORDS;       // NSTG * B_WORDS
    const uint32_t sB_u32 = smem_u32(sB);

    const int t = threadIdx.x, lane = t & 31, w = t >> 5;
    const int wm = w & 3, wn = w >> 2;
    const int gid = lane >> 2, tig = lane & 3;
    const int n0 = blockIdx.x * BM;

    // ---- stage A: x tile -> int8 fragments (once) ----
#pragma unroll
    for (int i = 0; i < 32; i++) {
        int wid = t + 512 * i;                    // 16384 words
        int row = wid >> 6, wk = wid & 63, k0 = wk * 4;
        float4 v = *(const float4*)(x + (size_t)(n0 + row) * DIM + k0);
        uint32_t pw = pack4(q8(v.x), q8(v.y), q8(v.z), q8(v.w));
        int mt = row >> 4, gr = row & 7, jr = (row >> 3) & 1;
        int c = k0 >> 5, hk = (k0 >> 4) & 1, tg = (k0 >> 2) & 3;
        sA[(((mt * 8 + c) * 32 + gr * 4 + tg) << 2) + jr + 2 * hk] = pw;
    }

    // ---- B ring prologue: stages 0..2 ----
#pragma unroll
    for (int s = 0; s < NSTG; s++) {
#pragma unroll
        for (int i = 0; i < 4; i++) {
            uint32_t off = (uint32_t)(t * 16 + i * 8192);   // bytes within 32KB
            cp16(sB_u32 + s * (B_WORDS * 4) + off,
                 (const char*)g_e8 + (size_t)s * 32768 + off);
        }
        CP_COMMIT();
    }
    __syncthreads();   // A visible to all warps

    uint32_t t2a0[8], t2b0[8], t2a1[8], t2b1[8];
#pragma unroll
    for (int s = 0; s < 8; s++) {
        t2a0[s] = t2b0[s] = t2a1[s] = t2b1[s] = 0xFFFFFFFFu;
    }

    for (int kt = 0; kt < NKT; kt++) {
        CP_WAIT2();
        __syncthreads();               // stage kt%3 data visible

        const uint32_t* bS = sB + (kt % NSTG) * B_WORDS;
        int acc[4][4][4];
#pragma unroll
        for (int m = 0; m < 4; m++)
#pragma unroll
            for (int nn = 0; nn < 4; nn++)
#pragma unroll
                for (int q = 0; q < 4; q++) acc[m][nn][q] = 0;

#pragma unroll
        for (int c = 0; c < 8; c++) {
            uint2 b[4];
#pragma unroll
            for (int nn = 0; nn < 4; nn++) {
                const int ntl = wn * 4 + nn;
                b[nn] = *(const uint2*)&bS[((ntl * 8 + c) * 32 + lane) << 1];
            }
#pragma unroll
            for (int m = 0; m < 4; m++) {
                const int mt = wm * 4 + m;
                uint4 av = *(const uint4*)&sA[((mt * 8 + c) * 32 + lane) << 2];
#pragma unroll
                for (int nn = 0; nn < 4; nn++)
                    imma16832(acc[m][nn], av.x, av.y, av.z, av.w, b[nn].x, b[nn].y);
            }
        }
        __syncthreads();               // all warps done with stage kt%3

        // refill ring
        if (kt + NSTG < NKT) {
#pragma unroll
            for (int i = 0; i < 4; i++) {
                uint32_t off = (uint32_t)(t * 16 + i * 8192);
                cp16(sB_u32 + ((kt + NSTG) % NSTG) * (B_WORDS * 4) + off,
                     (const char*)g_e8 + (size_t)(kt + NSTG) * 32768 + off);
            }
        }
        CP_COMMIT();

        // fold scores: s = e2s[col] - 2*xe (exact int32); pack (s+2^23)<<7 | loc
#pragma unroll
        for (int nn = 0; nn < 4; nn++) {
            const int colb = kt * 128 + (wn * 4 + nn) * 8 + tig * 2;
            const int e20 = __ldg(&g_e2s[colb]);
            const int e21 = __ldg(&g_e2s[colb + 1]);
            const uint32_t loc = (uint32_t)(kt * 4 + nn);
#pragma unroll
            for (int m = 0; m < 4; m++)
#pragma unroll
                for (int jr = 0; jr < 2; jr++) {
                    const int sl = m * 2 + jr;
                    {   // j = 0 stream
                        int s = e20 - 2 * acc[m][nn][jr * 2];
                        uint32_t p = ((uint32_t)(s + (1 << 23)) << 7) | loc;
                        if (p < t2a0[sl])      { t2b0[sl] = t2a0[sl]; t2a0[sl] = p; }
                        else if (p < t2b0[sl]) { t2b0[sl] = p; }
                    }
                    {   // j = 1 stream
                        int s = e21 - 2 * acc[m][nn][jr * 2 + 1];
                        uint32_t p = ((uint32_t)(s + (1 << 23)) << 7) | loc;
                        if (p < t2a1[sl])      { t2b1[sl] = t2a1[sl]; t2a1[sl] = p; }
                        else if (p < t2b1[sl]) { t2b1[sl] = p; }
                    }
                }
        }
    }

    // ---- emit 64 candidates per token row ----
#pragma unroll
    for (int m = 0; m < 4; m++)
#pragma unroll
        for (int jr = 0; jr < 2; jr++) {
            const int sl  = m * 2 + jr;
            const int row = n0 + wm * 64 + m * 16 + jr * 8 + gid;
            const int sb  = (wn * 4 + tig) * 4;
            uint32_t ps[4] = {t2a0[sl], t2b0[sl], t2a1[sl], t2b1[sl]};
#pragma unroll
            for (int u = 0; u < 4; u++) {
                const int j   = u >> 1;
                uint32_t p    = ps[u];
                int s   = (int)(p >> 7) - (1 << 23);
                int loc = (int)(p & 127);
                int col = (loc >> 2) * 128 + (wn * 4 + (loc & 3)) * 8 + tig * 2 + j;
                g_cand[row][sb + u] = make_int2(s, col);
            }
        }
}

// ---------------------------------------------------------------------------
// Rescore: warp per token. Top-16 of 64 candidates, exact fp32, gather winner.
// ---------------------------------------------------------------------------
__global__ __launch_bounds__(256)
void rescore_kernel(const float* __restrict__ x, const float* __restrict__ embed,
                    float* __restrict__ out) {
    const int tok  = (blockIdx.x * blockDim.x + threadIdx.x) >> 5;
    const int lane = threadIdx.x & 31;
    if (tok >= N_TOK) return;

    int2 c0 = g_cand[tok][lane];
    int2 c1 = g_cand[tok][lane + 32];
    long long p0 = ((long long)c0.x << 13) | (long long)c0.y;
    long long p1 = ((long long)c1.x << 13) | (long long)c1.y;
    if (p1 < p0) { long long tmp = p0; p0 = p1; p1 = tmp; }

    int sel[16];
#pragma unroll
    for (int r = 0; r < 16; r++) {
        long long mv = p0;
#pragma unroll
        for (int o = 16; o > 0; o >>= 1) {
            long long ov = __shfl_xor_sync(0xffffffffu, mv, o);
            if (ov < mv) mv = ov;
        }
        sel[r] = (int)(mv & 0x1FFF);
        if (p0 == mv) { p0 = p1; p1 = 0x7FFFFFFFFFFFFFFFLL; }
    }

    float xv[8];
#pragma unroll
    for (int q = 0; q < 8; q++) xv[q] = x[(size_t)tok * DIM + lane + 32 * q];

    float bv = 3.4e38f; int bk = KCODE;
#pragma unroll
    for (int r = 0; r < 16; r++) {
        const int k = sel[r];
        const float* e = embed + (size_t)k * DIM;
        float d = 0.f;
#pragma unroll
        for (int q = 0; q < 8; q++) d = fmaf(xv[q], e[lane + 32 * q], d);
#pragma unroll
        for (int o = 16; o > 0; o >>= 1) d += __shfl_xor_sync(0xffffffffu, d, o);
        float sc = fmaf(-2.f, d, g_e2[k]);
        if (sc < bv || (sc == bv && k < bk)) { bv = sc; bk = k; }
    }

    const float* e = embed + (size_t)bk * DIM;
#pragma unroll
    for (int q = 0; q < 8; q++)
        out[(size_t)tok * DIM + lane + 32 * q] = e[lane + 32 * q];
}

// ---------------------------------------------------------------------------
extern "C" void kernel_launch(void* const* d_in, const int* in_sizes, int n_in,
                              void* d_out, int out_size) {
    const float* x     = (const float*)d_in[0];
    const float* embed = (const float*)d_in[1];
    if (n_in >= 2 && in_sizes[0] < in_sizes[1]) {
        const float* tmp = x; x = embed; embed = tmp;
    }
    float* out = (float*)d_out;

    cudaFuncSetAttribute(screen_kernel, cudaFuncAttributeMaxDynamicSharedMemorySize, SMEM_TOTAL);

    equant_kernel<<<KCODE / 8, 256>>>(embed);
    screen_kernel<<<N_TOK / BM, 512, SMEM_TOTAL>>>(x);
    rescore_kernel<<<N_TOK / 8, 256>>>(x, embed, out);
}